// round 15
// baseline (speedup 1.0000x reference)
#include <cuda_runtime.h>
#include <cuda_fp16.h>

#define RES 2048
#define TBL_ENTRIES (RES * RES)

// 64 MB scratch: entry [y][x] = { (f[y][x][c], f[y+1][x][c]) packed as half2, c=0..2, pad }
__device__ uint4 g_vp[TBL_ENTRIES];

__device__ __forceinline__ unsigned pack2(float lo, float hi)
{
    __half2 h = __floats2half2_rn(lo, hi);
    return *reinterpret_cast<unsigned*>(&h);
}

// One thread builds 4 adjacent entries (x0 = 4m). Grid reads are 3 x LDG.128
// per row (16B-aligned since float offset = y*6144 + 12m), fully coalesced.
__global__ void __launch_bounds__(256) repack_kernel(const float4* __restrict__ grid4)
{
    int q = blockIdx.x * blockDim.x + threadIdx.x;     // quad index
    if (q >= TBL_ENTRIES / 4) return;

    int y  = q >> 9;                // q / 512   (512 quads per row)
    int m  = q & 511;               // quad within row
    int y1 = min(y + 1, RES - 1);

    // float4 index of the 12-float segment for x = 4m..4m+3
    const float4* r0 = grid4 + (size_t)y  * (RES * 3 / 4) + m * 3;
    const float4* r1 = grid4 + (size_t)y1 * (RES * 3 / 4) + m * 3;

    float4 t0 = __ldg(r0 + 0), t1 = __ldg(r0 + 1), t2 = __ldg(r0 + 2);  // row y
    float4 u0 = __ldg(r1 + 0), u1 = __ldg(r1 + 1), u2 = __ldg(r1 + 2);  // row y+1

    // row floats: t = {x:4m ch0,ch1,ch2 | x:4m+1 ch0 ...}
    float tr[12] = { t0.x, t0.y, t0.z, t0.w, t1.x, t1.y, t1.z, t1.w, t2.x, t2.y, t2.z, t2.w };
    float ur[12] = { u0.x, u0.y, u0.z, u0.w, u1.x, u1.y, u1.z, u1.w, u2.x, u2.y, u2.z, u2.w };

    unsigned long long pol;
    asm("createpolicy.fractional.L2::evict_last.b64 %0, 1.0;" : "=l"(pol));

    uint4* dst = &g_vp[(y << 11) + (m << 2)];
#pragma unroll
    for (int e = 0; e < 4; e++) {
        unsigned w0 = pack2(tr[e * 3 + 0], ur[e * 3 + 0]);
        unsigned w1 = pack2(tr[e * 3 + 1], ur[e * 3 + 1]);
        unsigned w2 = pack2(tr[e * 3 + 2], ur[e * 3 + 2]);
        asm volatile(
            "st.global.L2::cache_hint.v4.b32 [%0], {%1,%2,%3,%4}, %5;"
            :: "l"(dst + e), "r"(w0), "r"(w1), "r"(w2), "r"(0u), "l"(pol)
            : "memory");
    }
}

__global__ void __launch_bounds__(256) bilerp_kernel(
    const float* __restrict__ pts,    // [N,2]
    float* __restrict__ out,          // [N,3]
    int n)
{
    int i = blockIdx.x * blockDim.x + threadIdx.x;
    if (i >= n) return;

    // evict-first streaming read of the point
    float2 p = __ldcs(reinterpret_cast<const float2*>(pts) + i);

    const float scale = (float)(RES - 1);
    float sx = p.x * scale;
    float sy = p.y * scale;

    int xl = min(max((int)floorf(sx), 0), RES - 2);
    int yl = min(max((int)floorf(sy), 0), RES - 2);

    float tx = sx - (float)xl;
    float ty = sy - (float)yl;
    float omtx = 1.0f - tx;
    float omty = 1.0f - ty;

    int base = (yl << 11) + xl;

    // sticky-L2 table gathers via policy register
    unsigned long long pol;
    asm("createpolicy.fractional.L2::evict_last.b64 %0, 1.0;" : "=l"(pol));

    unsigned Lx, Ly, Lz, Lw, Rx, Ry, Rz, Rw;
    asm volatile(
        "ld.global.nc.L2::cache_hint.v4.b32 {%0,%1,%2,%3}, [%4], %5;"
        : "=r"(Lx), "=r"(Ly), "=r"(Lz), "=r"(Lw)
        : "l"(&g_vp[base]), "l"(pol));
    asm volatile(
        "ld.global.nc.L2::cache_hint.v4.b32 {%0,%1,%2,%3}, [%4], %5;"
        : "=r"(Rx), "=r"(Ry), "=r"(Rz), "=r"(Rw)
        : "l"(&g_vp[base + 1]), "l"(pol));
    (void)Lw; (void)Rw;

    float2 l0 = __half22float2(*reinterpret_cast<__half2*>(&Lx)); // (c00.0, c10.0)
    float2 l1 = __half22float2(*reinterpret_cast<__half2*>(&Ly));
    float2 l2 = __half22float2(*reinterpret_cast<__half2*>(&Lz));
    float2 r0 = __half22float2(*reinterpret_cast<__half2*>(&Rx)); // (c01.0, c11.0)
    float2 r1 = __half22float2(*reinterpret_cast<__half2*>(&Ry));
    float2 r2 = __half22float2(*reinterpret_cast<__half2*>(&Rz));

    float o0 = (l0.x * omtx + r0.x * tx) * omty + (l0.y * omtx + r0.y * tx) * ty;
    float o1 = (l1.x * omtx + r1.x * tx) * omty + (l1.y * omtx + r1.y * tx) * ty;
    float o2 = (l2.x * omtx + r2.x * tx) * omty + (l2.y * omtx + r2.y * tx) * ty;

    // evict-first streaming stores
    float* o = out + (size_t)i * 3;
    __stcs(o + 0, o0);
    __stcs(o + 1, o1);
    __stcs(o + 2, o2);
}

extern "C" void kernel_launch(void* const* d_in, const int* in_sizes, int n_in,
                              void* d_out, int out_size)
{
    const float* pts  = (const float*)d_in[0];
    const float* grid = (const float*)d_in[1];

    int threads = 256;

    int nquad = TBL_ENTRIES / 4;
    int rblocks = (nquad + threads - 1) / threads;
    repack_kernel<<<rblocks, threads>>>((const float4*)grid);

    int n = in_sizes[0] / 2;
    int blocks = (n + threads - 1) / threads;
    bilerp_kernel<<<blocks, threads>>>(pts, (float*)d_out, n);
}

// round 16
// speedup vs baseline: 1.0958x; 1.0958x over previous
#include <cuda_runtime.h>
#include <cuda_fp16.h>

#define RES 2048
#define TBL_ENTRIES (RES * RES)

// 64 MB scratch, 32B-aligned: entry [y][x] = {(f[y][x][c], f[y+1][x][c]) half2, c=0..2, pad}
__device__ __align__(32) uint4 g_vp[TBL_ENTRIES];

// ---- repack: exact round-14 scalar form (proven 17.5us, coalesced) ----
__global__ void __launch_bounds__(256) repack_kernel(const float* __restrict__ grid)
{
    int idx = blockIdx.x * blockDim.x + threadIdx.x;
    if (idx >= TBL_ENTRIES) return;

    int y = idx >> 11;
    int x = idx & (RES - 1);
    int y1 = min(y + 1, RES - 1);

    const float* p0 = grid + (size_t)idx * 3;
    const float* p1 = grid + ((size_t)(y1 << 11) + x) * 3;

    float a0 = __ldg(p0 + 0), a1 = __ldg(p0 + 1), a2 = __ldg(p0 + 2);
    float b0 = __ldg(p1 + 0), b1 = __ldg(p1 + 1), b2 = __ldg(p1 + 2);

    __half2 h0 = __floats2half2_rn(a0, b0);
    __half2 h1 = __floats2half2_rn(a1, b1);
    __half2 h2 = __floats2half2_rn(a2, b2);

    unsigned w0 = *reinterpret_cast<unsigned*>(&h0);
    unsigned w1 = *reinterpret_cast<unsigned*>(&h1);
    unsigned w2 = *reinterpret_cast<unsigned*>(&h2);

    unsigned long long pol;
    asm("createpolicy.fractional.L2::evict_last.b64 %0, 1.0;" : "=l"(pol));
    asm volatile(
        "st.global.L2::cache_hint.v4.b32 [%0], {%1,%2,%3,%4}, %5;"
        :: "l"(&g_vp[idx]), "r"(w0), "r"(w1), "r"(w2), "r"(0u), "l"(pol)
        : "memory");
}

__global__ void __launch_bounds__(256) bilerp_kernel(
    const float* __restrict__ pts,    // [N,2]
    float* __restrict__ out,          // [N,3]
    int n)
{
    int i = blockIdx.x * blockDim.x + threadIdx.x;
    if (i >= n) return;

    float2 p = __ldcs(reinterpret_cast<const float2*>(pts) + i);

    const float scale = (float)(RES - 1);
    float sx = p.x * scale;
    float sy = p.y * scale;

    int xl = min(max((int)floorf(sx), 0), RES - 2);
    int yl = min(max((int)floorf(sy), 0), RES - 2);

    float tx = sx - (float)xl;
    float ty = sy - (float)yl;
    float omtx = 1.0f - tx;
    float omty = 1.0f - ty;

    int base = (yl << 11) + xl;
    int aligned = base & ~1;               // 32B-aligned entry pair
    unsigned oddf = (unsigned)(base & 1);

    // one v8 (32B) load covers entries {aligned, aligned+1}
    unsigned a0, a1, a2, a3, a4, a5, a6, a7;
    asm volatile(
        "ld.global.nc.L2::evict_last.v8.b32 {%0,%1,%2,%3,%4,%5,%6,%7}, [%8];"
        : "=r"(a0), "=r"(a1), "=r"(a2), "=r"(a3),
          "=r"(a4), "=r"(a5), "=r"(a6), "=r"(a7)
        : "l"(g_vp + aligned));
    (void)a3; (void)a7;

    // when base is odd, R lives in the NEXT 32B pair: predicated second v8
    unsigned b0 = 0u, b1 = 0u, b2 = 0u, b3, b4, b5, b6, b7;
    asm volatile(
        "{\n\t"
        ".reg .pred p;\n\t"
        "setp.ne.u32 p, %9, 0;\n\t"
        "@p ld.global.nc.L2::evict_last.v8.b32 {%0,%1,%2,%3,%4,%5,%6,%7}, [%8];\n\t"
        "}"
        : "+r"(b0), "+r"(b1), "+r"(b2), "=r"(b3),
          "=r"(b4), "=r"(b5), "=r"(b6), "=r"(b7)
        : "l"(g_vp + (base + 1)), "r"(oddf));
    (void)b3; (void)b4; (void)b5; (void)b6; (void)b7;

    bool odd = oddf != 0u;
    // L = entry base:  even -> a0..a2 ; odd -> a4..a6
    unsigned Lx = odd ? a4 : a0;
    unsigned Ly = odd ? a5 : a1;
    unsigned Lz = odd ? a6 : a2;
    // R = entry base+1: even -> a4..a6 ; odd -> b0..b2
    unsigned Rx = odd ? b0 : a4;
    unsigned Ry = odd ? b1 : a5;
    unsigned Rz = odd ? b2 : a6;

    float2 l0 = __half22float2(*reinterpret_cast<__half2*>(&Lx)); // (c00.0, c10.0)
    float2 l1 = __half22float2(*reinterpret_cast<__half2*>(&Ly));
    float2 l2 = __half22float2(*reinterpret_cast<__half2*>(&Lz));
    float2 r0 = __half22float2(*reinterpret_cast<__half2*>(&Rx)); // (c01.0, c11.0)
    float2 r1 = __half22float2(*reinterpret_cast<__half2*>(&Ry));
    float2 r2 = __half22float2(*reinterpret_cast<__half2*>(&Rz));

    float o0 = (l0.x * omtx + r0.x * tx) * omty + (l0.y * omtx + r0.y * tx) * ty;
    float o1 = (l1.x * omtx + r1.x * tx) * omty + (l1.y * omtx + r1.y * tx) * ty;
    float o2 = (l2.x * omtx + r2.x * tx) * omty + (l2.y * omtx + r2.y * tx) * ty;

    float* o = out + (size_t)i * 3;
    __stcs(o + 0, o0);
    __stcs(o + 1, o1);
    __stcs(o + 2, o2);
}

extern "C" void kernel_launch(void* const* d_in, const int* in_sizes, int n_in,
                              void* d_out, int out_size)
{
    const float* pts  = (const float*)d_in[0];
    const float* grid = (const float*)d_in[1];

    int threads = 256;

    int rblocks = (TBL_ENTRIES + threads - 1) / threads;
    repack_kernel<<<rblocks, threads>>>(grid);

    int n = in_sizes[0] / 2;
    int blocks = (n + threads - 1) / threads;
    bilerp_kernel<<<blocks, threads>>>(pts, (float*)d_out, n);
}